// round 10
// baseline (speedup 1.0000x reference)
#include <cuda_runtime.h>
#include <cuda_bf16.h>
#include <math.h>
#include <cstdint>

#define D_MODEL 1024
#define HEADS   16
#define DH      64
#define SEQ     1024
#define BATCH   8
#define MROWS   (BATCH*SEQ)   // 8192

typedef __nv_bfloat16 bf16;

// ---- scratch (no cudaMalloc allowed) ----
__device__ bf16 g_xh[MROWS*D_MODEL];
__device__ bf16 g_xl[MROWS*D_MODEL];
__device__ bf16 g_Qh[MROWS*D_MODEL];
__device__ bf16 g_Ql[MROWS*D_MODEL];
__device__ bf16 g_Kh[MROWS*D_MODEL];
__device__ bf16 g_Kl[MROWS*D_MODEL];
__device__ bf16 g_Vh[MROWS*D_MODEL];
__device__ bf16 g_Vl[MROWS*D_MODEL];
__device__ bf16 g_Oh[MROWS*D_MODEL];
__device__ bf16 g_Ol[MROWS*D_MODEL];
__device__ bf16 g_Wh[4][D_MODEL*D_MODEL];  // natural [k][n]
__device__ bf16 g_Wl[4][D_MODEL*D_MODEL];

#define QSC (0.125f * 1.44269504088896f)   // 1/sqrt(dh) * log2(e)

// ============================================================
// PTX helpers (sm_80-era only; tcgen05 unavailable at .target sm_103)
// ============================================================
__device__ __forceinline__ uint32_t smem_u32(const void* p) {
    uint32_t a;
    asm("{ .reg .u64 t; cvta.to.shared.u64 t, %1; cvt.u32.u64 %0, t; }"
        : "=r"(a) : "l"(p));
    return a;
}
__device__ __forceinline__ void cpa16(uint32_t dst, const void* src) {
    asm volatile("cp.async.cg.shared.global [%0], [%1], 16;"
                 :: "r"(dst), "l"(src) : "memory");
}
#define CP_COMMIT() asm volatile("cp.async.commit_group;" ::: "memory")
#define CP_WAIT1()  asm volatile("cp.async.wait_group 1;" ::: "memory")
#define CP_WAIT0()  asm volatile("cp.async.wait_group 0;" ::: "memory")

__device__ __forceinline__ void ldsm_x4(uint32_t* r, uint32_t addr) {
    asm volatile("ldmatrix.sync.aligned.m8n8.x4.shared.b16 {%0,%1,%2,%3}, [%4];"
                 : "=r"(r[0]), "=r"(r[1]), "=r"(r[2]), "=r"(r[3]) : "r"(addr));
}
__device__ __forceinline__ void ldsm_x4t(uint32_t* r, uint32_t addr) {
    asm volatile("ldmatrix.sync.aligned.m8n8.x4.trans.shared.b16 {%0,%1,%2,%3}, [%4];"
                 : "=r"(r[0]), "=r"(r[1]), "=r"(r[2]), "=r"(r[3]) : "r"(addr));
}
__device__ __forceinline__ void mma16816(float* c, const uint32_t* a,
                                         uint32_t b0, uint32_t b1) {
    asm volatile(
        "mma.sync.aligned.m16n8k16.row.col.f32.bf16.bf16.f32 "
        "{%0,%1,%2,%3}, {%4,%5,%6,%7}, {%8,%9}, {%0,%1,%2,%3};"
        : "+f"(c[0]), "+f"(c[1]), "+f"(c[2]), "+f"(c[3])
        : "r"(a[0]), "r"(a[1]), "r"(a[2]), "r"(a[3]), "r"(b0), "r"(b1));
}
__device__ __forceinline__ float ex2f(float x) {
    float r; asm("ex2.approx.f32 %0, %1;" : "=f"(r) : "f"(x)); return r;
}
__device__ __forceinline__ uint32_t pk2(float lo, float hi) {   // bf16x2 {lo,hi}
    uint32_t d;
    asm("cvt.rn.bf16x2.f32 %0, %1, %2;" : "=r"(d) : "f"(hi), "f"(lo));
    return d;
}
__device__ __forceinline__ float2 upk2(uint32_t v) {
    __nv_bfloat162 t = *reinterpret_cast<__nv_bfloat162*>(&v);
    return __bfloat1622float2(t);
}

// ============================================================
// splits: fp32 -> bf16 hi/lo
// ============================================================
__device__ __forceinline__ void split4(const float* __restrict__ X,
                                       bf16* __restrict__ Xh,
                                       bf16* __restrict__ Xl, size_t i) {
    float4 v = *(const float4*)&X[i];
    float a[4] = {v.x, v.y, v.z, v.w};
    bf16 h[4], l[4];
    #pragma unroll
    for (int j = 0; j < 4; j++) {
        h[j] = __float2bfloat16_rn(a[j]);
        l[j] = __float2bfloat16_rn(a[j] - __bfloat162float(h[j]));
    }
    *(__nv_bfloat162*)&Xh[i]     = __halves2bfloat162(h[0], h[1]);
    *(__nv_bfloat162*)&Xh[i + 2] = __halves2bfloat162(h[2], h[3]);
    *(__nv_bfloat162*)&Xl[i]     = __halves2bfloat162(l[0], l[1]);
    *(__nv_bfloat162*)&Xl[i + 2] = __halves2bfloat162(l[2], l[3]);
}
__global__ void fsplit(const float* __restrict__ X,
                       bf16* __restrict__ Xh, bf16* __restrict__ Xl) {
    size_t i = (size_t)(blockIdx.x * blockDim.x + threadIdx.x) * 4;
    split4(X, Xh, Xl, i);
}
__global__ void wsplit4(const float* __restrict__ w0, const float* __restrict__ w1,
                        const float* __restrict__ w2, const float* __restrict__ w3,
                        bf16* __restrict__ Wh, bf16* __restrict__ Wl) {
    int z = blockIdx.z;
    const float* W = (z == 0) ? w0 : (z == 1) ? w1 : (z == 2) ? w2 : w3;
    size_t off = (size_t)z * D_MODEL * D_MODEL;
    size_t i = (size_t)(blockIdx.x * blockDim.x + threadIdx.x) * 4;
    split4(W, Wh + off, Wl + off, i);
}

// ============================================================
// hgemm7: C[M,1024] = A @ W via bf16 3-split on mma.sync.
//   Fused 3-term passes (R9, proven), but BK=32 with a THREE-stage
//   cp.async ring: 2 stages in flight, finer-grained waits, and only
//   ONE __syncthreads per stage (wait -> sync -> issue next -> compute;
//   the sync proves all warps left stage s-1, whose slot the new load
//   targets).
//   CTA 256x128, 8 warps (4m x 2n) of 64x64.
//   MODE 1: QKV fused via grid.z (bf16 hi/lo out, scaled).
//   MODE 0: fp32 out (final projection).
// ============================================================
#define AST32 80                        // A smem row stride (40 bf16)
#define BST   272                       // B smem row stride (136 bf16)
#define ABYT32 (256 * AST32)            // 20480
#define BBYT32 (32 * BST)               // 8704
#define STG32 (2 * ABYT32 + 2 * BBYT32) // 58368
#define NSTAGE 32                       // K chunks of 32
#define GEM_SMEM (3 * STG32)            // 175104

__device__ __forceinline__ void gload32(uint32_t st,
    const bf16* __restrict__ Ah, const bf16* __restrict__ Al,
    const bf16* __restrict__ Bh, const bf16* __restrict__ Bl,
    int m0, int n0, int kk0, int tid)
{
    #pragma unroll
    for (int t = 0; t < 4; t++) {            // A: 256x32, hi+lo
        int idx = tid + (t << 8);
        int r = idx >> 2, c = idx & 3;
        size_t go = (size_t)(m0 + r) * D_MODEL + kk0 + c * 8;
        uint32_t so = st + r * AST32 + c * 16;
        cpa16(so, Ah + go);
        cpa16(so + ABYT32, Al + go);
    }
    #pragma unroll
    for (int t = 0; t < 2; t++) {            // B: 32x128, hi+lo
        int idx = tid + (t << 8);
        int r = idx >> 4, c = idx & 15;
        size_t go = (size_t)(kk0 + r) * D_MODEL + n0 + c * 8;
        uint32_t so = st + 2 * ABYT32 + r * BST + c * 16;
        cpa16(so, Bh + go);
        cpa16(so + BBYT32, Bl + go);
    }
}

// fused 3-term pass over one BK=32 chunk (2 k16 steps)
__device__ __forceinline__ void gpass32(float acc[32][4],
    uint32_t aH, uint32_t aL, uint32_t bH, uint32_t bL,
    int wm, int wn, int lr, int lc)
{
    #pragma unroll
    for (int k16 = 0; k16 < 2; k16++) {
        uint32_t ah[4][4], al[4][4];
        #pragma unroll
        for (int mt = 0; mt < 4; mt++) {
            uint32_t aoff = (wm * 64 + mt * 16 + lr) * AST32 + k16 * 32 + lc * 16;
            ldsm_x4(ah[mt], aH + aoff);
            ldsm_x4(al[mt], aL + aoff);
        }
        #pragma unroll
        for (int cg = 0; cg < 4; cg++) {
            uint32_t boff = (k16 * 16 + lr) * BST + wn * 128 + cg * 32 + lc * 16;
            uint32_t bh4[4], bl4[4];
            ldsm_x4t(bh4, bH + boff);
            ldsm_x4t(bl4, bL + boff);
            #pragma unroll
            for (int half = 0; half < 2; half++) {
                const int nt = cg * 2 + half;
                const uint32_t h0 = bh4[half * 2], h1 = bh4[half * 2 + 1];
                const uint32_t l0 = bl4[half * 2], l1 = bl4[half * 2 + 1];
                #pragma unroll
                for (int mt = 0; mt < 4; mt++) {
                    mma16816(acc[mt * 8 + nt], ah[mt], h0, h1);
                    mma16816(acc[mt * 8 + nt], ah[mt], l0, l1);
                    mma16816(acc[mt * 8 + nt], al[mt], h0, h1);
                }
            }
        }
    }
}

template<int MODE>
__global__ __launch_bounds__(256, 1) void hgemm7(
    const bf16* __restrict__ Ah, const bf16* __restrict__ Al,
    const bf16* __restrict__ BhB, const bf16* __restrict__ BlB,
    float* __restrict__ C,
    bf16* __restrict__ Ch0, bf16* __restrict__ Cl0,
    bf16* __restrict__ Ch1, bf16* __restrict__ Cl1,
    bf16* __restrict__ Ch2, bf16* __restrict__ Cl2)
{
    extern __shared__ char dsm[];
    const uint32_t sb = smem_u32(dsm);

    const int tid = threadIdx.x;
    const int wid = tid >> 5;
    const int lane = tid & 31;
    const int wm = wid >> 1, wn = wid & 1;
    const int lr = lane & 15, lc = lane >> 4;
    const int m0 = blockIdx.y << 8;
    const int n0 = blockIdx.x << 7;
    const int z  = blockIdx.z;

    const bf16* Bh = BhB + (size_t)z * D_MODEL * D_MODEL;
    const bf16* Bl = BlB + (size_t)z * D_MODEL * D_MODEL;

    float acc[32][4];
    #pragma unroll
    for (int i = 0; i < 32; i++)
        #pragma unroll
        for (int j = 0; j < 4; j++) acc[i][j] = 0.f;

    // prologue: 2 stages in flight
    gload32(sb,         Ah, Al, Bh, Bl, m0, n0, 0,  tid);
    CP_COMMIT();
    gload32(sb + STG32, Ah, Al, Bh, Bl, m0, n0, 32, tid);
    CP_COMMIT();

    #pragma unroll 1
    for (int s = 0; s < NSTAGE; s++) {
        if (s < NSTAGE - 2) CP_WAIT1();
        else                CP_WAIT0();
        __syncthreads();                       // single barrier per stage
        if (s + 2 < NSTAGE) {
            int slot = (s + 2) % 3;
            gload32(sb + slot * STG32, Ah, Al, Bh, Bl,
                    m0, n0, (s + 2) << 5, tid);
            CP_COMMIT();
        }
        const uint32_t base = sb + (s % 3) * STG32;
        gpass32(acc, base, base + ABYT32,
                base + 2 * ABYT32, base + 2 * ABYT32 + BBYT32,
                wm, wn, lr, lc);
    }

    const int g = lane >> 2, tg = lane & 3;
    const float scale = (MODE == 1 && z == 0) ? QSC : 1.0f;
    bf16* Ch = (z == 0) ? Ch0 : (z == 1) ? Ch1 : Ch2;
    bf16* Cl = (z == 0) ? Cl0 : (z == 1) ? Cl1 : Cl2;

    #pragma unroll
    for (int mt = 0; mt < 4; mt++) {
        int row = m0 + wm * 64 + mt * 16 + g;
        #pragma unroll
        for (int nt = 0; nt < 8; nt++) {
            int col = n0 + wn * 64 + nt * 8 + tg * 2;
            float* ac = acc[mt * 8 + nt];
            if (MODE == 0) {
                float* cp = &C[(size_t)row * D_MODEL + col];
                *(float2*)cp = make_float2(ac[0], ac[1]);
                *(float2*)(cp + 8 * D_MODEL) = make_float2(ac[2], ac[3]);
            } else {
                float v0 = ac[0] * scale, v1 = ac[1] * scale;
                float v2 = ac[2] * scale, v3 = ac[3] * scale;
                uint32_t h01 = pk2(v0, v1), h23 = pk2(v2, v3);
                float2 f01 = upk2(h01), f23 = upk2(h23);
                size_t o0 = (size_t)row * D_MODEL + col;
                size_t o1 = o0 + 8 * D_MODEL;
                *(uint32_t*)&Ch[o0] = h01;
                *(uint32_t*)&Ch[o1] = h23;
                *(uint32_t*)&Cl[o0] = pk2(v0 - f01.x, v1 - f01.y);
                *(uint32_t*)&Cl[o1] = pk2(v2 - f23.x, v3 - f23.y);
            }
        }
    }
}

// ============================================================
// attn_mma2 (R7, unchanged): flash attention on mma.sync,
// bf16 3-split both GEMMs, 256 queries/CTA, 32 q-rows/warp.
// ============================================================
#define AST 144
#define QTB  (256 * AST)                 // one 256x64 bf16 Q tile = 36864
#define KVB  (64 * AST)                  // one 64x64 bf16 tile = 9216
#define KVST (4 * KVB)                   // Kh,Kl,Vh,Vl per stage = 36864
#define KVOFF (2 * QTB)                  // 73728
#define ATT_SMEM (KVOFF + 2 * KVST)      // 147456

__device__ __forceinline__ void kvload(uint32_t st,
    const bf16* __restrict__ Kh, const bf16* __restrict__ Kl,
    const bf16* __restrict__ Vh, const bf16* __restrict__ Vl,
    size_t gbase, int tid)
{
    #pragma unroll
    for (int t = 0; t < 2; t++) {
        int idx = tid + (t << 8);
        int r = idx >> 3, c = idx & 7;
        size_t go = gbase + (size_t)r * D_MODEL + c * 8;
        uint32_t so = st + r * AST + c * 16;
        cpa16(so,           Kh + go);
        cpa16(so + KVB,     Kl + go);
        cpa16(so + 2 * KVB, Vh + go);
        cpa16(so + 3 * KVB, Vl + go);
    }
}

__global__ __launch_bounds__(256, 1) void attn_mma2(
    const bf16* __restrict__ Qh, const bf16* __restrict__ Ql,
    const bf16* __restrict__ Kh, const bf16* __restrict__ Kl,
    const bf16* __restrict__ Vh, const bf16* __restrict__ Vl,
    bf16* __restrict__ Oh, bf16* __restrict__ Ol)
{
    extern __shared__ char dsm[];
    const uint32_t sb = smem_u32(dsm);

    const int tid = threadIdx.x;
    const int wid = tid >> 5;
    const int lane = tid & 31;
    const int lr = lane & 15, lc = lane >> 4;
    const int g = lane >> 2, tg = lane & 3;
    const int qb = blockIdx.x, h = blockIdx.y, b = blockIdx.z;
    const size_t qrow0 = (size_t)(b * SEQ + qb * 256);
    const size_t hcol = h * DH;

    #pragma unroll
    for (int t = 0; t < 8; t++) {
        int idx = tid + (t << 8);
        int r = idx >> 3, c = idx & 7;
        size_t go = (qrow0 + r) * D_MODEL + hcol + c * 8;
        uint32_t so = sb + r * AST + c * 16;
        cpa16(so, Qh + go);
        cpa16(so + QTB, Ql + go);
    }
    CP_COMMIT();

    kvload(sb + KVOFF, Kh, Kl, Vh, Vl, (size_t)(b * SEQ) * D_MODEL + hcol, tid);
    CP_COMMIT();

    float acco[16][4];
    #pragma unroll
    for (int i = 0; i < 16; i++)
        #pragma unroll
        for (int j = 0; j < 4; j++) acco[i][j] = 0.f;
    float mrow[4] = {-1e30f, -1e30f, -1e30f, -1e30f};
    float lrow[4] = {0.f, 0.f, 0.f, 0.f};

    #pragma unroll 1
    for (int kb = 0; kb < 16; kb++) {
        if (kb < 15)
            kvload(sb + KVOFF + ((kb + 1) & 1) * KVST, Kh, Kl, Vh, Vl,
                   (size_t)(b * SEQ + (kb + 1) * 64) * D_MODEL + hcol, tid);
        CP_COMMIT();
        CP_WAIT1();
        __syncthreads();

        const uint32_t kst = sb + KVOFF + (kb & 1) * KVST;
        const uint32_t khT = kst, klT = kst + KVB;
        const uint32_t vhT = kst + 2 * KVB, vlT = kst + 3 * KVB;

        float accs[16][4];
        #pragma unroll
        for (int i = 0; i < 16; i++)
            #pragma unroll
            for (int j = 0; j < 4; j++) accs[i][j] = 0.f;

        #pragma unroll
        for (int kt = 0; kt < 4; kt++) {
            uint32_t ah[2][4], al[2][4], kfh[4][4], kfl[4][4];
            #pragma unroll
            for (int mt = 0; mt < 2; mt++) {
                uint32_t qoff = (wid * 32 + mt * 16 + lr) * AST + kt * 32 + lc * 16;
                ldsm_x4(ah[mt], sb + qoff);
                ldsm_x4(al[mt], sb + QTB + qoff);
            }
            #pragma unroll
            for (int j = 0; j < 4; j++) {
                uint32_t koff = (j * 16 + lr) * AST + kt * 32 + lc * 16;
                ldsm_x4(kfh[j], khT + koff);
                ldsm_x4(kfl[j], klT + koff);
            }
            #pragma unroll
            for (int mt = 0; mt < 2; mt++)
                #pragma unroll
                for (int j = 0; j < 4; j++) {
                    float* c0 = accs[mt * 8 + 2 * j];
                    float* c1 = accs[mt * 8 + 2 * j + 1];
                    mma16816(c0, ah[mt], kfh[j][0], kfh[j][2]);
                    mma16816(c1, ah[mt], kfh[j][1], kfh[j][3]);
                    mma16816(c0, ah[mt], kfl[j][0], kfl[j][2]);
                    mma16816(c1, ah[mt], kfl[j][1], kfl[j][3]);
                    mma16816(c0, al[mt], kfh[j][0], kfh[j][2]);
                    mma16816(c1, al[mt], kfh[j][1], kfh[j][3]);
                }
        }

        #pragma unroll
        for (int mt = 0; mt < 2; mt++) {
            float mx0 = -1e30f, mx1 = -1e30f;
            #pragma unroll
            for (int nt = 0; nt < 8; nt++) {
                mx0 = fmaxf(mx0, fmaxf(accs[mt * 8 + nt][0], accs[mt * 8 + nt][1]));
                mx1 = fmaxf(mx1, fmaxf(accs[mt * 8 + nt][2], accs[mt * 8 + nt][3]));
            }
            mx0 = fmaxf(mx0, __shfl_xor_sync(0xffffffffu, mx0, 1));
            mx0 = fmaxf(mx0, __shfl_xor_sync(0xffffffffu, mx0, 2));
            mx1 = fmaxf(mx1, __shfl_xor_sync(0xffffffffu, mx1, 1));
            mx1 = fmaxf(mx1, __shfl_xor_sync(0xffffffffu, mx1, 2));
            float mn0 = fmaxf(mrow[mt * 2],     mx0);
            float mn1 = fmaxf(mrow[mt * 2 + 1], mx1);
            float al0 = ex2f(mrow[mt * 2]     - mn0);
            float al1 = ex2f(mrow[mt * 2 + 1] - mn1);
            mrow[mt * 2] = mn0; mrow[mt * 2 + 1] = mn1;
            float s0 = 0.f, s1 = 0.f;
            #pragma unroll
            for (int nt = 0; nt < 8; nt++) {
                float* a = accs[mt * 8 + nt];
                a[0] = ex2f(a[0] - mn0);
                a[1] = ex2f(a[1] - mn0);
                a[2] = ex2f(a[2] - mn1);
                a[3] = ex2f(a[3] - mn1);
                s0 += a[0] + a[1];
                s1 += a[2] + a[3];
            }
            s0 += __shfl_xor_sync(0xffffffffu, s0, 1);
            s0 += __shfl_xor_sync(0xffffffffu, s0, 2);
            s1 += __shfl_xor_sync(0xffffffffu, s1, 1);
            s1 += __shfl_xor_sync(0xffffffffu, s1, 2);
            lrow[mt * 2]     = lrow[mt * 2]     * al0 + s0;
            lrow[mt * 2 + 1] = lrow[mt * 2 + 1] * al1 + s1;
            #pragma unroll
            for (int nt = 0; nt < 8; nt++) {
                acco[mt * 8 + nt][0] *= al0; acco[mt * 8 + nt][1] *= al0;
                acco[mt * 8 + nt][2] *= al1; acco[mt * 8 + nt][3] *= al1;
            }
        }

        #pragma unroll
        for (int kt = 0; kt < 4; kt++) {
            uint32_t vbh[4][4], vbl[4][4];
            #pragma unroll
            for (int cg = 0; cg < 4; cg++) {
                uint32_t voff = (kt * 16 + lr) * AST + cg * 32 + lc * 16;
                ldsm_x4t(vbh[cg], vhT + voff);
                ldsm_x4t(vbl[cg], vlT + voff);
            }
            #pragma unroll
            for (int mt = 0; mt < 2; mt++) {
                float* s0 = accs[mt * 8 + 2 * kt];
                float* s1 = accs[mt * 8 + 2 * kt + 1];
                uint32_t ph[4], pl[4];
                ph[0] = pk2(s0[0], s0[1]);
                ph[1] = pk2(s0[2], s0[3]);
                ph[2] = pk2(s1[0], s1[1]);
                ph[3] = pk2(s1[2], s1[3]);
                float2 f0 = upk2(ph[0]), f1 = upk2(ph[1]);
                float2 f2 = upk2(ph[2]), f3 = upk2(ph[3]);
                pl[0] = pk2(s0[0] - f0.x, s0[1] - f0.y);
                pl[1] = pk2(s0[2] - f1.x, s0[3] - f1.y);
                pl[2] = pk2(s1[0] - f2.x, s1[1] - f2.y);
                pl[3] = pk2(s1[2] - f3.x, s1[3] - f3.y);
                #pragma unroll
                for (int nt = 0; nt < 8; nt++) {
                    uint32_t h0 = vbh[nt >> 1][(nt & 1) * 2];
                    uint32_t h1 = vbh[nt >> 1][(nt & 1) * 2 + 1];
                    mma16816(acco[mt * 8 + nt], ph, h0, h1);
                    mma16816(acco[mt * 8 + nt], pl, h0, h1);
                    mma16816(acco[mt * 8 + nt], ph,
                             vbl[nt >> 1][(nt & 1) * 2],
                             vbl[nt >> 1][(nt & 1) * 2 + 1]);
                }
            }
        }
        __syncthreads();
    }

    #pragma unroll
    for (int mt = 0; mt < 2; mt++) {
        float inv0 = 1.f / lrow[mt * 2];
        float inv1 = 1.f / lrow[mt * 2 + 1];
        size_t r0 = (qrow0 + wid * 32 + mt * 16 + g) * D_MODEL + hcol;
        size_t r1 = r0 + 8 * D_MODEL;
        #pragma unroll
        for (int nt = 0; nt < 8; nt++) {
            int col = nt * 8 + tg * 2;
            float v0 = acco[mt * 8 + nt][0] * inv0;
            float v1 = acco[mt * 8 + nt][1] * inv0;
            float v2 = acco[mt * 8 + nt][2] * inv1;
            float v3 = acco[mt * 8 + nt][3] * inv1;
            uint32_t h01 = pk2(v0, v1), h23 = pk2(v2, v3);
            float2 f01 = upk2(h01), f23 = upk2(h23);
            *(uint32_t*)&Oh[r0 + col] = h01;
            *(uint32_t*)&Oh[r1 + col] = h23;
            *(uint32_t*)&Ol[r0 + col] = pk2(v0 - f01.x, v1 - f01.y);
            *(uint32_t*)&Ol[r1 + col] = pk2(v2 - f23.x, v3 - f23.y);
        }
    }
}

// ============================================================
extern "C" void kernel_launch(void* const* d_in, const int* in_sizes, int n_in,
                              void* d_out, int out_size)
{
    const float* x = (const float*)d_in[0];
    float* out = (float*)d_out;

    bf16 *xh, *xl, *qh, *ql, *kh, *kl, *vh, *vl, *oh, *ol, *bh, *bl;
    cudaGetSymbolAddress((void**)&xh, g_xh);
    cudaGetSymbolAddress((void**)&xl, g_xl);
    cudaGetSymbolAddress((void**)&qh, g_Qh);
    cudaGetSymbolAddress((void**)&ql, g_Ql);
    cudaGetSymbolAddress((void**)&kh, g_Kh);
    cudaGetSymbolAddress((void**)&kl, g_Kl);
    cudaGetSymbolAddress((void**)&vh, g_Vh);
    cudaGetSymbolAddress((void**)&vl, g_Vl);
    cudaGetSymbolAddress((void**)&oh, g_Oh);
    cudaGetSymbolAddress((void**)&ol, g_Ol);
    cudaGetSymbolAddress((void**)&bh, g_Wh);
    cudaGetSymbolAddress((void**)&bl, g_Wl);
    const size_t WSTR = (size_t)D_MODEL * D_MODEL;

    static int cfg_done = 0;
    if (!cfg_done) {
        cudaFuncSetAttribute(hgemm7<0>,
            cudaFuncAttributeMaxDynamicSharedMemorySize, GEM_SMEM);
        cudaFuncSetAttribute(hgemm7<1>,
            cudaFuncAttributeMaxDynamicSharedMemorySize, GEM_SMEM);
        cudaFuncSetAttribute(attn_mma2,
            cudaFuncAttributeMaxDynamicSharedMemorySize, ATT_SMEM);
        cfg_done = 1;
    }

    // splits: x, then all 4 weights in one launch
    fsplit<<<MROWS * D_MODEL / 1024, 256>>>(x, xh, xl);
    wsplit4<<<dim3(D_MODEL * D_MODEL / 1024, 1, 4), 256>>>(
        (const float*)d_in[1], (const float*)d_in[2],
        (const float*)d_in[3], (const float*)d_in[4], bh, bl);

    // QKV projections fused into one launch (grid.z selects W / output)
    hgemm7<1><<<dim3(D_MODEL / 128, MROWS / 256, 3), 256, GEM_SMEM>>>(
        xh, xl, bh, bl, nullptr, qh, ql, kh, kl, vh, vl);

    attn_mma2<<<dim3(SEQ / 256, HEADS, BATCH), 256, ATT_SMEM>>>(
        qh, ql, kh, kl, vh, vl, oh, ol);

    // final projection (W index 3)
    hgemm7<0><<<dim3(D_MODEL / 128, MROWS / 256, 1), 256, GEM_SMEM>>>(
        oh, ol, bh + 3 * WSTR, bl + 3 * WSTR, out,
        nullptr, nullptr, nullptr, nullptr, nullptr, nullptr);
}

// round 11
// speedup vs baseline: 1.0134x; 1.0134x over previous
#include <cuda_runtime.h>
#include <cuda_bf16.h>
#include <math.h>
#include <cstdint>

#define D_MODEL 1024
#define HEADS   16
#define DH      64
#define SEQ     1024
#define BATCH   8
#define MROWS   (BATCH*SEQ)   // 8192

typedef __nv_bfloat16 bf16;

// ---- scratch (no cudaMalloc allowed) ----
__device__ bf16 g_xh[MROWS*D_MODEL];
__device__ bf16 g_xl[MROWS*D_MODEL];
__device__ bf16 g_Qh[MROWS*D_MODEL];
__device__ bf16 g_Ql[MROWS*D_MODEL];
__device__ bf16 g_Kh[MROWS*D_MODEL];
__device__ bf16 g_Kl[MROWS*D_MODEL];
__device__ bf16 g_Vh[MROWS*D_MODEL];
__device__ bf16 g_Vl[MROWS*D_MODEL];
__device__ bf16 g_Oh[MROWS*D_MODEL];
__device__ bf16 g_Ol[MROWS*D_MODEL];
__device__ bf16 g_Wh[4][D_MODEL*D_MODEL];  // natural [k][n]
__device__ bf16 g_Wl[4][D_MODEL*D_MODEL];

#define QSC (0.125f * 1.44269504088896f)   // 1/sqrt(dh) * log2(e)

// ============================================================
// PTX helpers (sm_80-era only; tcgen05 unavailable at .target sm_103)
// ============================================================
__device__ __forceinline__ uint32_t smem_u32(const void* p) {
    uint32_t a;
    asm("{ .reg .u64 t; cvta.to.shared.u64 t, %1; cvt.u32.u64 %0, t; }"
        : "=r"(a) : "l"(p));
    return a;
}
__device__ __forceinline__ void cpa16(uint32_t dst, const void* src) {
    asm volatile("cp.async.cg.shared.global [%0], [%1], 16;"
                 :: "r"(dst), "l"(src) : "memory");
}
#define CP_COMMIT() asm volatile("cp.async.commit_group;" ::: "memory")
#define CP_WAIT1()  asm volatile("cp.async.wait_group 1;" ::: "memory")
#define CP_WAIT0()  asm volatile("cp.async.wait_group 0;" ::: "memory")

__device__ __forceinline__ void ldsm_x4(uint32_t* r, uint32_t addr) {
    asm volatile("ldmatrix.sync.aligned.m8n8.x4.shared.b16 {%0,%1,%2,%3}, [%4];"
                 : "=r"(r[0]), "=r"(r[1]), "=r"(r[2]), "=r"(r[3]) : "r"(addr));
}
__device__ __forceinline__ void ldsm_x4t(uint32_t* r, uint32_t addr) {
    asm volatile("ldmatrix.sync.aligned.m8n8.x4.trans.shared.b16 {%0,%1,%2,%3}, [%4];"
                 : "=r"(r[0]), "=r"(r[1]), "=r"(r[2]), "=r"(r[3]) : "r"(addr));
}
__device__ __forceinline__ void mma16816(float* c, const uint32_t* a,
                                         uint32_t b0, uint32_t b1) {
    asm volatile(
        "mma.sync.aligned.m16n8k16.row.col.f32.bf16.bf16.f32 "
        "{%0,%1,%2,%3}, {%4,%5,%6,%7}, {%8,%9}, {%0,%1,%2,%3};"
        : "+f"(c[0]), "+f"(c[1]), "+f"(c[2]), "+f"(c[3])
        : "r"(a[0]), "r"(a[1]), "r"(a[2]), "r"(a[3]), "r"(b0), "r"(b1));
}
__device__ __forceinline__ float ex2f(float x) {
    float r; asm("ex2.approx.f32 %0, %1;" : "=f"(r) : "f"(x)); return r;
}
__device__ __forceinline__ uint32_t pk2(float lo, float hi) {   // bf16x2 {lo,hi}
    uint32_t d;
    asm("cvt.rn.bf16x2.f32 %0, %1, %2;" : "=r"(d) : "f"(hi), "f"(lo));
    return d;
}
__device__ __forceinline__ float2 upk2(uint32_t v) {
    __nv_bfloat162 t = *reinterpret_cast<__nv_bfloat162*>(&v);
    return __bfloat1622float2(t);
}

// ============================================================
// splits: fp32 -> bf16 hi/lo
// ============================================================
__device__ __forceinline__ void split4(const float* __restrict__ X,
                                       bf16* __restrict__ Xh,
                                       bf16* __restrict__ Xl, size_t i) {
    float4 v = *(const float4*)&X[i];
    float a[4] = {v.x, v.y, v.z, v.w};
    bf16 h[4], l[4];
    #pragma unroll
    for (int j = 0; j < 4; j++) {
        h[j] = __float2bfloat16_rn(a[j]);
        l[j] = __float2bfloat16_rn(a[j] - __bfloat162float(h[j]));
    }
    *(__nv_bfloat162*)&Xh[i]     = __halves2bfloat162(h[0], h[1]);
    *(__nv_bfloat162*)&Xh[i + 2] = __halves2bfloat162(h[2], h[3]);
    *(__nv_bfloat162*)&Xl[i]     = __halves2bfloat162(l[0], l[1]);
    *(__nv_bfloat162*)&Xl[i + 2] = __halves2bfloat162(l[2], l[3]);
}
__global__ void fsplit(const float* __restrict__ X,
                       bf16* __restrict__ Xh, bf16* __restrict__ Xl) {
    size_t i = (size_t)(blockIdx.x * blockDim.x + threadIdx.x) * 4;
    split4(X, Xh, Xl, i);
}
__global__ void wsplit4(const float* __restrict__ w0, const float* __restrict__ w1,
                        const float* __restrict__ w2, const float* __restrict__ w3,
                        bf16* __restrict__ Wh, bf16* __restrict__ Wl) {
    int z = blockIdx.z;
    const float* W = (z == 0) ? w0 : (z == 1) ? w1 : (z == 2) ? w2 : w3;
    size_t off = (size_t)z * D_MODEL * D_MODEL;
    size_t i = (size_t)(blockIdx.x * blockDim.x + threadIdx.x) * 4;
    split4(W, Wh + off, Wl + off, i);
}

// ============================================================
// hgemm8: C[M,1024] = A @ W via bf16 3-split on mma.sync.
//   = R9's hgemm6 (best-known staging: 4-tile BK=64 chunks, 2-stage
//   ring) with the mma issue order made TERM-OUTER inside each column
//   group: all 8 accs get term1, then term2, then term3. Same-acc
//   reuse distance 1 -> 8 to cover HMMA accumulate latency.
//   CTA 256x128, 8 warps (4m x 2n) of 64x64.
// ============================================================
#define AST 144                         // A smem row stride bytes (72 bf16)
#define BST 272                         // B smem row stride bytes (136 bf16)
#define ABYT (256 * AST)                // 36864
#define BBYT (64 * BST)                 // 17408
#define STG4 (2 * ABYT + 2 * BBYT)      // 108544
#define GEM_SMEM (2 * STG4)             // 217088

__device__ __forceinline__ void gload4(uint32_t st,
    const bf16* __restrict__ Ah, const bf16* __restrict__ Al,
    const bf16* __restrict__ Bh, const bf16* __restrict__ Bl,
    int m0, int n0, int kk0, int tid)
{
    #pragma unroll
    for (int t = 0; t < 8; t++) {            // A: 256x64, hi+lo
        int idx = tid + (t << 8);
        int r = idx >> 3, c = idx & 7;
        size_t go = (size_t)(m0 + r) * D_MODEL + kk0 + c * 8;
        uint32_t so = st + r * AST + c * 16;
        cpa16(so, Ah + go);
        cpa16(so + ABYT, Al + go);
    }
    #pragma unroll
    for (int t = 0; t < 4; t++) {            // B: 64x128, hi+lo
        int idx = tid + (t << 8);
        int r = idx >> 4, c = idx & 15;
        size_t go = (size_t)(kk0 + r) * D_MODEL + n0 + c * 8;
        uint32_t so = st + 2 * ABYT + r * BST + c * 16;
        cpa16(so, Bh + go);
        cpa16(so + BBYT, Bl + go);
    }
}

// fused 3-term pass, term-outer mma ordering
__device__ __forceinline__ void gpass3(float acc[32][4],
    uint32_t aH, uint32_t aL, uint32_t bH, uint32_t bL,
    int wm, int wn, int lr, int lc)
{
    #pragma unroll
    for (int k16 = 0; k16 < 4; k16++) {
        uint32_t ah[4][4], al[4][4];
        #pragma unroll
        for (int mt = 0; mt < 4; mt++) {
            uint32_t aoff = (wm * 64 + mt * 16 + lr) * AST + k16 * 32 + lc * 16;
            ldsm_x4(ah[mt], aH + aoff);
            ldsm_x4(al[mt], aL + aoff);
        }
        #pragma unroll
        for (int cg = 0; cg < 4; cg++) {
            uint32_t boff = (k16 * 16 + lr) * BST + wn * 128 + cg * 32 + lc * 16;
            uint32_t bh4[4], bl4[4];
            ldsm_x4t(bh4, bH + boff);
            ldsm_x4t(bl4, bL + boff);
            // term 1: Ah * Bh  (8 independent accs)
            #pragma unroll
            for (int half = 0; half < 2; half++)
                #pragma unroll
                for (int mt = 0; mt < 4; mt++)
                    mma16816(acc[mt * 8 + cg * 2 + half], ah[mt],
                             bh4[half * 2], bh4[half * 2 + 1]);
            // term 2: Ah * Bl
            #pragma unroll
            for (int half = 0; half < 2; half++)
                #pragma unroll
                for (int mt = 0; mt < 4; mt++)
                    mma16816(acc[mt * 8 + cg * 2 + half], ah[mt],
                             bl4[half * 2], bl4[half * 2 + 1]);
            // term 3: Al * Bh
            #pragma unroll
            for (int half = 0; half < 2; half++)
                #pragma unroll
                for (int mt = 0; mt < 4; mt++)
                    mma16816(acc[mt * 8 + cg * 2 + half], al[mt],
                             bh4[half * 2], bh4[half * 2 + 1]);
        }
    }
}

template<int MODE>
__global__ __launch_bounds__(256) void hgemm8(
    const bf16* __restrict__ Ah, const bf16* __restrict__ Al,
    const bf16* __restrict__ BhB, const bf16* __restrict__ BlB,
    float* __restrict__ C,
    bf16* __restrict__ Ch0, bf16* __restrict__ Cl0,
    bf16* __restrict__ Ch1, bf16* __restrict__ Cl1,
    bf16* __restrict__ Ch2, bf16* __restrict__ Cl2)
{
    extern __shared__ char dsm[];
    const uint32_t sb = smem_u32(dsm);

    const int tid = threadIdx.x;
    const int wid = tid >> 5;
    const int lane = tid & 31;
    const int wm = wid >> 1, wn = wid & 1;
    const int lr = lane & 15, lc = lane >> 4;
    const int m0 = blockIdx.y << 8;
    const int n0 = blockIdx.x << 7;
    const int z  = blockIdx.z;

    const bf16* Bh = BhB + (size_t)z * D_MODEL * D_MODEL;
    const bf16* Bl = BlB + (size_t)z * D_MODEL * D_MODEL;

    float acc[32][4];
    #pragma unroll
    for (int i = 0; i < 32; i++)
        #pragma unroll
        for (int j = 0; j < 4; j++) acc[i][j] = 0.f;

    gload4(sb, Ah, Al, Bh, Bl, m0, n0, 0, tid);
    CP_COMMIT();

    #pragma unroll 1
    for (int s = 0; s < 16; s++) {
        if (s < 15) {
            gload4(sb + ((s + 1) & 1) * STG4, Ah, Al, Bh, Bl,
                   m0, n0, (s + 1) << 6, tid);
            CP_COMMIT();
            CP_WAIT1();
        } else {
            CP_WAIT0();
        }
        __syncthreads();

        const uint32_t base = sb + (s & 1) * STG4;
        gpass3(acc, base, base + ABYT, base + 2 * ABYT, base + 2 * ABYT + BBYT,
               wm, wn, lr, lc);
        __syncthreads();
    }

    const int g = lane >> 2, tg = lane & 3;
    const float scale = (MODE == 1 && z == 0) ? QSC : 1.0f;
    bf16* Ch = (z == 0) ? Ch0 : (z == 1) ? Ch1 : Ch2;
    bf16* Cl = (z == 0) ? Cl0 : (z == 1) ? Cl1 : Cl2;

    #pragma unroll
    for (int mt = 0; mt < 4; mt++) {
        int row = m0 + wm * 64 + mt * 16 + g;
        #pragma unroll
        for (int nt = 0; nt < 8; nt++) {
            int col = n0 + wn * 64 + nt * 8 + tg * 2;
            float* ac = acc[mt * 8 + nt];
            if (MODE == 0) {
                float* cp = &C[(size_t)row * D_MODEL + col];
                *(float2*)cp = make_float2(ac[0], ac[1]);
                *(float2*)(cp + 8 * D_MODEL) = make_float2(ac[2], ac[3]);
            } else {
                float v0 = ac[0] * scale, v1 = ac[1] * scale;
                float v2 = ac[2] * scale, v3 = ac[3] * scale;
                uint32_t h01 = pk2(v0, v1), h23 = pk2(v2, v3);
                float2 f01 = upk2(h01), f23 = upk2(h23);
                size_t o0 = (size_t)row * D_MODEL + col;
                size_t o1 = o0 + 8 * D_MODEL;
                *(uint32_t*)&Ch[o0] = h01;
                *(uint32_t*)&Ch[o1] = h23;
                *(uint32_t*)&Cl[o0] = pk2(v0 - f01.x, v1 - f01.y);
                *(uint32_t*)&Cl[o1] = pk2(v2 - f23.x, v3 - f23.y);
            }
        }
    }
}

// ============================================================
// attn_mma3: attn_mma2 with TERM-OUTER mma ordering in both the
// S (QK^T) and PV loops. Same-acc reuse distance 2 -> 16 (S) and
// 3 -> 16 (PV).
// ============================================================
#define QTB  (256 * AST)                 // one 256x64 bf16 Q tile = 36864
#define KVB  (64 * AST)                  // one 64x64 bf16 tile = 9216
#define KVST (4 * KVB)                   // Kh,Kl,Vh,Vl per stage = 36864
#define KVOFF (2 * QTB)                  // 73728
#define ATT_SMEM (KVOFF + 2 * KVST)      // 147456

__device__ __forceinline__ void kvload(uint32_t st,
    const bf16* __restrict__ Kh, const bf16* __restrict__ Kl,
    const bf16* __restrict__ Vh, const bf16* __restrict__ Vl,
    size_t gbase, int tid)
{
    #pragma unroll
    for (int t = 0; t < 2; t++) {
        int idx = tid + (t << 8);
        int r = idx >> 3, c = idx & 7;
        size_t go = gbase + (size_t)r * D_MODEL + c * 8;
        uint32_t so = st + r * AST + c * 16;
        cpa16(so,           Kh + go);
        cpa16(so + KVB,     Kl + go);
        cpa16(so + 2 * KVB, Vh + go);
        cpa16(so + 3 * KVB, Vl + go);
    }
}

__global__ __launch_bounds__(256, 1) void attn_mma3(
    const bf16* __restrict__ Qh, const bf16* __restrict__ Ql,
    const bf16* __restrict__ Kh, const bf16* __restrict__ Kl,
    const bf16* __restrict__ Vh, const bf16* __restrict__ Vl,
    bf16* __restrict__ Oh, bf16* __restrict__ Ol)
{
    extern __shared__ char dsm[];
    const uint32_t sb = smem_u32(dsm);

    const int tid = threadIdx.x;
    const int wid = tid >> 5;
    const int lane = tid & 31;
    const int lr = lane & 15, lc = lane >> 4;
    const int g = lane >> 2, tg = lane & 3;
    const int qb = blockIdx.x, h = blockIdx.y, b = blockIdx.z;
    const size_t qrow0 = (size_t)(b * SEQ + qb * 256);
    const size_t hcol = h * DH;

    #pragma unroll
    for (int t = 0; t < 8; t++) {
        int idx = tid + (t << 8);
        int r = idx >> 3, c = idx & 7;
        size_t go = (qrow0 + r) * D_MODEL + hcol + c * 8;
        uint32_t so = sb + r * AST + c * 16;
        cpa16(so, Qh + go);
        cpa16(so + QTB, Ql + go);
    }
    CP_COMMIT();

    kvload(sb + KVOFF, Kh, Kl, Vh, Vl, (size_t)(b * SEQ) * D_MODEL + hcol, tid);
    CP_COMMIT();

    float acco[16][4];
    #pragma unroll
    for (int i = 0; i < 16; i++)
        #pragma unroll
        for (int j = 0; j < 4; j++) acco[i][j] = 0.f;
    float mrow[4] = {-1e30f, -1e30f, -1e30f, -1e30f};
    float lrow[4] = {0.f, 0.f, 0.f, 0.f};

    #pragma unroll 1
    for (int kb = 0; kb < 16; kb++) {
        if (kb < 15)
            kvload(sb + KVOFF + ((kb + 1) & 1) * KVST, Kh, Kl, Vh, Vl,
                   (size_t)(b * SEQ + (kb + 1) * 64) * D_MODEL + hcol, tid);
        CP_COMMIT();
        CP_WAIT1();
        __syncthreads();

        const uint32_t kst = sb + KVOFF + (kb & 1) * KVST;
        const uint32_t khT = kst, klT = kst + KVB;
        const uint32_t vhT = kst + 2 * KVB, vlT = kst + 3 * KVB;

        float accs[16][4];
        #pragma unroll
        for (int i = 0; i < 16; i++)
            #pragma unroll
            for (int j = 0; j < 4; j++) accs[i][j] = 0.f;

        #pragma unroll
        for (int kt = 0; kt < 4; kt++) {
            uint32_t ah[2][4], al[2][4], kfh[4][4], kfl[4][4];
            #pragma unroll
            for (int mt = 0; mt < 2; mt++) {
                uint32_t qoff = (wid * 32 + mt * 16 + lr) * AST + kt * 32 + lc * 16;
                ldsm_x4(ah[mt], sb + qoff);
                ldsm_x4(al[mt], sb + QTB + qoff);
            }
            #pragma unroll
            for (int j = 0; j < 4; j++) {
                uint32_t koff = (j * 16 + lr) * AST + kt * 32 + lc * 16;
                ldsm_x4(kfh[j], khT + koff);
                ldsm_x4(kfl[j], klT + koff);
            }
            // term 1: Qh * Kh  (all 16 accs)
            #pragma unroll
            for (int mt = 0; mt < 2; mt++)
                #pragma unroll
                for (int j = 0; j < 4; j++) {
                    mma16816(accs[mt * 8 + 2 * j],     ah[mt], kfh[j][0], kfh[j][2]);
                    mma16816(accs[mt * 8 + 2 * j + 1], ah[mt], kfh[j][1], kfh[j][3]);
                }
            // term 2: Qh * Kl
            #pragma unroll
            for (int mt = 0; mt < 2; mt++)
                #pragma unroll
                for (int j = 0; j < 4; j++) {
                    mma16816(accs[mt * 8 + 2 * j],     ah[mt], kfl[j][0], kfl[j][2]);
                    mma16816(accs[mt * 8 + 2 * j + 1], ah[mt], kfl[j][1], kfl[j][3]);
                }
            // term 3: Ql * Kh
            #pragma unroll
            for (int mt = 0; mt < 2; mt++)
                #pragma unroll
                for (int j = 0; j < 4; j++) {
                    mma16816(accs[mt * 8 + 2 * j],     al[mt], kfh[j][0], kfh[j][2]);
                    mma16816(accs[mt * 8 + 2 * j + 1], al[mt], kfh[j][1], kfh[j][3]);
                }
        }

        #pragma unroll
        for (int mt = 0; mt < 2; mt++) {
            float mx0 = -1e30f, mx1 = -1e30f;
            #pragma unroll
            for (int nt = 0; nt < 8; nt++) {
                mx0 = fmaxf(mx0, fmaxf(accs[mt * 8 + nt][0], accs[mt * 8 + nt][1]));
                mx1 = fmaxf(mx1, fmaxf(accs[mt * 8 + nt][2], accs[mt * 8 + nt][3]));
            }
            mx0 = fmaxf(mx0, __shfl_xor_sync(0xffffffffu, mx0, 1));
            mx0 = fmaxf(mx0, __shfl_xor_sync(0xffffffffu, mx0, 2));
            mx1 = fmaxf(mx1, __shfl_xor_sync(0xffffffffu, mx1, 1));
            mx1 = fmaxf(mx1, __shfl_xor_sync(0xffffffffu, mx1, 2));
            float mn0 = fmaxf(mrow[mt * 2],     mx0);
            float mn1 = fmaxf(mrow[mt * 2 + 1], mx1);
            float al0 = ex2f(mrow[mt * 2]     - mn0);
            float al1 = ex2f(mrow[mt * 2 + 1] - mn1);
            mrow[mt * 2] = mn0; mrow[mt * 2 + 1] = mn1;
            float s0 = 0.f, s1 = 0.f;
            #pragma unroll
            for (int nt = 0; nt < 8; nt++) {
                float* a = accs[mt * 8 + nt];
                a[0] = ex2f(a[0] - mn0);
                a[1] = ex2f(a[1] - mn0);
                a[2] = ex2f(a[2] - mn1);
                a[3] = ex2f(a[3] - mn1);
                s0 += a[0] + a[1];
                s1 += a[2] + a[3];
            }
            s0 += __shfl_xor_sync(0xffffffffu, s0, 1);
            s0 += __shfl_xor_sync(0xffffffffu, s0, 2);
            s1 += __shfl_xor_sync(0xffffffffu, s1, 1);
            s1 += __shfl_xor_sync(0xffffffffu, s1, 2);
            lrow[mt * 2]     = lrow[mt * 2]     * al0 + s0;
            lrow[mt * 2 + 1] = lrow[mt * 2 + 1] * al1 + s1;
            #pragma unroll
            for (int nt = 0; nt < 8; nt++) {
                acco[mt * 8 + nt][0] *= al0; acco[mt * 8 + nt][1] *= al0;
                acco[mt * 8 + nt][2] *= al1; acco[mt * 8 + nt][3] *= al1;
            }
        }

        // ---- O += P V, 3-split, term-outer ----
        #pragma unroll
        for (int kt = 0; kt < 4; kt++) {
            uint32_t vbh[4][4], vbl[4][4];
            #pragma unroll
            for (int cg = 0; cg < 4; cg++) {
                uint32_t voff = (kt * 16 + lr) * AST + cg * 32 + lc * 16;
                ldsm_x4t(vbh[cg], vhT + voff);
                ldsm_x4t(vbl[cg], vlT + voff);
            }
            // pack P for both mt first (kept alive through the term loops)
            uint32_t ph[2][4], pl[2][4];
            #pragma unroll
            for (int mt = 0; mt < 2; mt++) {
                float* s0 = accs[mt * 8 + 2 * kt];
                float* s1 = accs[mt * 8 + 2 * kt + 1];
                ph[mt][0] = pk2(s0[0], s0[1]);
                ph[mt][1] = pk2(s0[2], s0[3]);
                ph[mt][2] = pk2(s1[0], s1[1]);
                ph[mt][3] = pk2(s1[2], s1[3]);
                float2 f0 = upk2(ph[mt][0]), f1 = upk2(ph[mt][1]);
                float2 f2 = upk2(ph[mt][2]), f3 = upk2(ph[mt][3]);
                pl[mt][0] = pk2(s0[0] - f0.x, s0[1] - f0.y);
                pl[mt][1] = pk2(s0[2] - f1.x, s0[3] - f1.y);
                pl[mt][2] = pk2(s1[0] - f2.x, s1[1] - f2.y);
                pl[mt][3] = pk2(s1[2] - f3.x, s1[3] - f3.y);
            }
            // term 1: Ph * Vh
            #pragma unroll
            for (int mt = 0; mt < 2; mt++)
                #pragma unroll
                for (int nt = 0; nt < 8; nt++)
                    mma16816(acco[mt * 8 + nt], ph[mt],
                             vbh[nt >> 1][(nt & 1) * 2],
                             vbh[nt >> 1][(nt & 1) * 2 + 1]);
            // term 2: Pl * Vh
            #pragma unroll
            for (int mt = 0; mt < 2; mt++)
                #pragma unroll
                for (int nt = 0; nt < 8; nt++)
                    mma16816(acco[mt * 8 + nt], pl[mt],
                             vbh[nt >> 1][(nt & 1) * 2],
                             vbh[nt >> 1][(nt & 1) * 2 + 1]);
            // term 3: Ph * Vl
            #pragma unroll
            for (int mt = 0; mt < 2; mt++)
                #pragma unroll
                for (int nt = 0; nt < 8; nt++)
                    mma16816(acco[mt * 8 + nt], ph[mt],
                             vbl[nt >> 1][(nt & 1) * 2],
                             vbl[nt >> 1][(nt & 1) * 2 + 1]);
        }
        __syncthreads();
    }

    #pragma unroll
    for (int mt = 0; mt < 2; mt++) {
        float inv0 = 1.f / lrow[mt * 2];
        float inv1 = 1.f / lrow[mt * 2 + 1];
        size_t r0 = (qrow0 + wid * 32 + mt * 16 + g) * D_MODEL + hcol;
        size_t r1 = r0 + 8 * D_MODEL;
        #pragma unroll
        for (int nt = 0; nt < 8; nt++) {
            int col = nt * 8 + tg * 2;
            float v0 = acco[mt * 8 + nt][0] * inv0;
            float v1 = acco[mt * 8 + nt][1] * inv0;
            float v2 = acco[mt * 8 + nt][2] * inv1;
            float v3 = acco[mt * 8 + nt][3] * inv1;
            uint32_t h01 = pk2(v0, v1), h23 = pk2(v2, v3);
            float2 f01 = upk2(h01), f23 = upk2(h23);
            *(uint32_t*)&Oh[r0 + col] = h01;
            *(uint32_t*)&Oh[r1 + col] = h23;
            *(uint32_t*)&Ol[r0 + col] = pk2(v0 - f01.x, v1 - f01.y);
            *(uint32_t*)&Ol[r1 + col] = pk2(v2 - f23.x, v3 - f23.y);
        }
    }
}

// ============================================================
extern "C" void kernel_launch(void* const* d_in, const int* in_sizes, int n_in,
                              void* d_out, int out_size)
{
    const float* x = (const float*)d_in[0];
    float* out = (float*)d_out;

    bf16 *xh, *xl, *qh, *ql, *kh, *kl, *vh, *vl, *oh, *ol, *bh, *bl;
    cudaGetSymbolAddress((void**)&xh, g_xh);
    cudaGetSymbolAddress((void**)&xl, g_xl);
    cudaGetSymbolAddress((void**)&qh, g_Qh);
    cudaGetSymbolAddress((void**)&ql, g_Ql);
    cudaGetSymbolAddress((void**)&kh, g_Kh);
    cudaGetSymbolAddress((void**)&kl, g_Kl);
    cudaGetSymbolAddress((void**)&vh, g_Vh);
    cudaGetSymbolAddress((void**)&vl, g_Vl);
    cudaGetSymbolAddress((void**)&oh, g_Oh);
    cudaGetSymbolAddress((void**)&ol, g_Ol);
    cudaGetSymbolAddress((void**)&bh, g_Wh);
    cudaGetSymbolAddress((void**)&bl, g_Wl);
    const size_t WSTR = (size_t)D_MODEL * D_MODEL;

    static int cfg_done = 0;
    if (!cfg_done) {
        cudaFuncSetAttribute(hgemm8<0>,
            cudaFuncAttributeMaxDynamicSharedMemorySize, GEM_SMEM);
        cudaFuncSetAttribute(hgemm8<1>,
            cudaFuncAttributeMaxDynamicSharedMemorySize, GEM_SMEM);
        cudaFuncSetAttribute(attn_mma3,
            cudaFuncAttributeMaxDynamicSharedMemorySize, ATT_SMEM);
        cfg_done = 1;
    }

    // splits: x, then all 4 weights in one launch
    fsplit<<<MROWS * D_MODEL / 1024, 256>>>(x, xh, xl);
    wsplit4<<<dim3(D_MODEL * D_MODEL / 1024, 1, 4), 256>>>(
        (const float*)d_in[1], (const float*)d_in[2],
        (const float*)d_in[3], (const float*)d_in[4], bh, bl);

    // QKV projections fused into one launch (grid.z selects W / output)
    hgemm8<1><<<dim3(D_MODEL / 128, MROWS / 256, 3), 256, GEM_SMEM>>>(
        xh, xl, bh, bl, nullptr, qh, ql, kh, kl, vh, vl);

    attn_mma3<<<dim3(SEQ / 256, HEADS, BATCH), 256, ATT_SMEM>>>(
        qh, ql, kh, kl, vh, vl, oh, ol);

    // final projection (W index 3)
    hgemm8<0><<<dim3(D_MODEL / 128, MROWS / 256, 1), 256, GEM_SMEM>>>(
        oh, ol, bh + 3 * WSTR, bl + 3 * WSTR, out,
        nullptr, nullptr, nullptr, nullptr, nullptr, nullptr);
}

// round 12
// speedup vs baseline: 1.1511x; 1.1360x over previous
#include <cuda_runtime.h>
#include <cuda_bf16.h>
#include <math.h>
#include <cstdint>

#define D_MODEL 1024
#define HEADS   16
#define DH      64
#define SEQ     1024
#define BATCH   8
#define MROWS   (BATCH*SEQ)   // 8192

typedef __nv_bfloat16 bf16;

// ---- scratch (no cudaMalloc allowed) ----
__device__ bf16 g_xh[MROWS*D_MODEL];
__device__ bf16 g_xl[MROWS*D_MODEL];
__device__ bf16 g_Qh[MROWS*D_MODEL];
__device__ bf16 g_Ql[MROWS*D_MODEL];
__device__ bf16 g_Kh[MROWS*D_MODEL];
__device__ bf16 g_Kl[MROWS*D_MODEL];
__device__ bf16 g_Vh[MROWS*D_MODEL];
__device__ bf16 g_Vl[MROWS*D_MODEL];
__device__ bf16 g_Oh[MROWS*D_MODEL];
__device__ bf16 g_Ol[MROWS*D_MODEL];
__device__ bf16 g_Wh[4][D_MODEL*D_MODEL];  // natural [k][n]
__device__ bf16 g_Wl[4][D_MODEL*D_MODEL];

#define QSC (0.125f * 1.44269504088896f)   // 1/sqrt(dh) * log2(e)

// ============================================================
// PTX helpers (sm_80-era only; tcgen05 unavailable at .target sm_103)
// ============================================================
__device__ __forceinline__ uint32_t smem_u32(const void* p) {
    uint32_t a;
    asm("{ .reg .u64 t; cvta.to.shared.u64 t, %1; cvt.u32.u64 %0, t; }"
        : "=r"(a) : "l"(p));
    return a;
}
__device__ __forceinline__ void cpa16(uint32_t dst, const void* src) {
    asm volatile("cp.async.cg.shared.global [%0], [%1], 16;"
                 :: "r"(dst), "l"(src) : "memory");
}
#define CP_COMMIT() asm volatile("cp.async.commit_group;" ::: "memory")
#define CP_WAIT1()  asm volatile("cp.async.wait_group 1;" ::: "memory")
#define CP_WAIT0()  asm volatile("cp.async.wait_group 0;" ::: "memory")

__device__ __forceinline__ void ldsm_x4(uint32_t* r, uint32_t addr) {
    asm volatile("ldmatrix.sync.aligned.m8n8.x4.shared.b16 {%0,%1,%2,%3}, [%4];"
                 : "=r"(r[0]), "=r"(r[1]), "=r"(r[2]), "=r"(r[3]) : "r"(addr));
}
__device__ __forceinline__ void ldsm_x4t(uint32_t* r, uint32_t addr) {
    asm volatile("ldmatrix.sync.aligned.m8n8.x4.trans.shared.b16 {%0,%1,%2,%3}, [%4];"
                 : "=r"(r[0]), "=r"(r[1]), "=r"(r[2]), "=r"(r[3]) : "r"(addr));
}
__device__ __forceinline__ void mma16816(float* c, const uint32_t* a,
                                         uint32_t b0, uint32_t b1) {
    asm volatile(
        "mma.sync.aligned.m16n8k16.row.col.f32.bf16.bf16.f32 "
        "{%0,%1,%2,%3}, {%4,%5,%6,%7}, {%8,%9}, {%0,%1,%2,%3};"
        : "+f"(c[0]), "+f"(c[1]), "+f"(c[2]), "+f"(c[3])
        : "r"(a[0]), "r"(a[1]), "r"(a[2]), "r"(a[3]), "r"(b0), "r"(b1));
}
__device__ __forceinline__ float ex2f(float x) {
    float r; asm("ex2.approx.f32 %0, %1;" : "=f"(r) : "f"(x)); return r;
}
__device__ __forceinline__ uint32_t pk2(float lo, float hi) {   // bf16x2 {lo,hi}
    uint32_t d;
    asm("cvt.rn.bf16x2.f32 %0, %1, %2;" : "=r"(d) : "f"(hi), "f"(lo));
    return d;
}
__device__ __forceinline__ float2 upk2(uint32_t v) {
    __nv_bfloat162 t = *reinterpret_cast<__nv_bfloat162*>(&v);
    return __bfloat1622float2(t);
}

// ============================================================
// splits: fp32 -> bf16 hi/lo
// ============================================================
__device__ __forceinline__ void split4(const float* __restrict__ X,
                                       bf16* __restrict__ Xh,
                                       bf16* __restrict__ Xl, size_t i) {
    float4 v = *(const float4*)&X[i];
    float a[4] = {v.x, v.y, v.z, v.w};
    bf16 h[4], l[4];
    #pragma unroll
    for (int j = 0; j < 4; j++) {
        h[j] = __float2bfloat16_rn(a[j]);
        l[j] = __float2bfloat16_rn(a[j] - __bfloat162float(h[j]));
    }
    *(__nv_bfloat162*)&Xh[i]     = __halves2bfloat162(h[0], h[1]);
    *(__nv_bfloat162*)&Xh[i + 2] = __halves2bfloat162(h[2], h[3]);
    *(__nv_bfloat162*)&Xl[i]     = __halves2bfloat162(l[0], l[1]);
    *(__nv_bfloat162*)&Xl[i + 2] = __halves2bfloat162(l[2], l[3]);
}
__global__ void fsplit(const float* __restrict__ X,
                       bf16* __restrict__ Xh, bf16* __restrict__ Xl) {
    size_t i = (size_t)(blockIdx.x * blockDim.x + threadIdx.x) * 4;
    split4(X, Xh, Xl, i);
}
__global__ void wsplit4(const float* __restrict__ w0, const float* __restrict__ w1,
                        const float* __restrict__ w2, const float* __restrict__ w3,
                        bf16* __restrict__ Wh, bf16* __restrict__ Wl) {
    int z = blockIdx.z;
    const float* W = (z == 0) ? w0 : (z == 1) ? w1 : (z == 2) ? w2 : w3;
    size_t off = (size_t)z * D_MODEL * D_MODEL;
    size_t i = (size_t)(blockIdx.x * blockDim.x + threadIdx.x) * 4;
    split4(W, Wh + off, Wl + off, i);
}

// ============================================================
// hgemm9: C[M,1024] = A @ W via bf16 3-split on mma.sync.
//   CTA 128x128, 8 warps (4m x 2n) of 32x64 — smem 111KB ->
//   TWO CTAs PER SM (4 warps/SMSP), so one CTA's load/sync phases
//   overlap the other's mma. BK=32, 3-stage ring, fused term-outer.
// ============================================================
#define AST9 80                         // A smem row stride (40 bf16)
#define BST  272                        // B smem row stride (136 bf16)
#define ABYT9 (128 * AST9)              // 10240
#define BBYT9 (32 * BST)                // 8704
#define STG9 (2 * ABYT9 + 2 * BBYT9)    // 37888
#define NST9 32                         // K chunks of 32
#define GEM_SMEM (3 * STG9)             // 113664  -> 2 CTAs/SM

__device__ __forceinline__ void gload9(uint32_t st,
    const bf16* __restrict__ Ah, const bf16* __restrict__ Al,
    const bf16* __restrict__ Bh, const bf16* __restrict__ Bl,
    int m0, int n0, int kk0, int tid)
{
    #pragma unroll
    for (int t = 0; t < 2; t++) {            // A: 128x32, hi+lo (512 chunks)
        int idx = tid + (t << 8);
        int r = idx >> 2, c = idx & 3;
        size_t go = (size_t)(m0 + r) * D_MODEL + kk0 + c * 8;
        uint32_t so = st + r * AST9 + c * 16;
        cpa16(so, Ah + go);
        cpa16(so + ABYT9, Al + go);
    }
    #pragma unroll
    for (int t = 0; t < 2; t++) {            // B: 32x128, hi+lo (512 chunks)
        int idx = tid + (t << 8);
        int r = idx >> 4, c = idx & 15;
        size_t go = (size_t)(kk0 + r) * D_MODEL + n0 + c * 8;
        uint32_t so = st + 2 * ABYT9 + r * BST + c * 16;
        cpa16(so, Bh + go);
        cpa16(so + BBYT9, Bl + go);
    }
}

// fused 3-term pass over one BK=32 chunk, term-outer
__device__ __forceinline__ void gpass9(float acc[16][4],
    uint32_t aH, uint32_t aL, uint32_t bH, uint32_t bL,
    int wm, int wn, int lr, int lc)
{
    #pragma unroll
    for (int k16 = 0; k16 < 2; k16++) {
        uint32_t ah[2][4], al[2][4];
        #pragma unroll
        for (int mt = 0; mt < 2; mt++) {
            uint32_t aoff = (wm * 32 + mt * 16 + lr) * AST9 + k16 * 32 + lc * 16;
            ldsm_x4(ah[mt], aH + aoff);
            ldsm_x4(al[mt], aL + aoff);
        }
        #pragma unroll
        for (int cg = 0; cg < 4; cg++) {
            uint32_t boff = (k16 * 16 + lr) * BST + wn * 128 + cg * 32 + lc * 16;
            uint32_t bh4[4], bl4[4];
            ldsm_x4t(bh4, bH + boff);
            ldsm_x4t(bl4, bL + boff);
            // term 1: Ah*Bh
            #pragma unroll
            for (int half = 0; half < 2; half++)
                #pragma unroll
                for (int mt = 0; mt < 2; mt++)
                    mma16816(acc[mt * 8 + cg * 2 + half], ah[mt],
                             bh4[half * 2], bh4[half * 2 + 1]);
            // term 2: Ah*Bl
            #pragma unroll
            for (int half = 0; half < 2; half++)
                #pragma unroll
                for (int mt = 0; mt < 2; mt++)
                    mma16816(acc[mt * 8 + cg * 2 + half], ah[mt],
                             bl4[half * 2], bl4[half * 2 + 1]);
            // term 3: Al*Bh
            #pragma unroll
            for (int half = 0; half < 2; half++)
                #pragma unroll
                for (int mt = 0; mt < 2; mt++)
                    mma16816(acc[mt * 8 + cg * 2 + half], al[mt],
                             bh4[half * 2], bh4[half * 2 + 1]);
        }
    }
}

template<int MODE>
__global__ __launch_bounds__(256, 2) void hgemm9(
    const bf16* __restrict__ Ah, const bf16* __restrict__ Al,
    const bf16* __restrict__ BhB, const bf16* __restrict__ BlB,
    float* __restrict__ C,
    bf16* __restrict__ Ch0, bf16* __restrict__ Cl0,
    bf16* __restrict__ Ch1, bf16* __restrict__ Cl1,
    bf16* __restrict__ Ch2, bf16* __restrict__ Cl2)
{
    extern __shared__ char dsm[];
    const uint32_t sb = smem_u32(dsm);

    const int tid = threadIdx.x;
    const int wid = tid >> 5;
    const int lane = tid & 31;
    const int wm = wid >> 1, wn = wid & 1;
    const int lr = lane & 15, lc = lane >> 4;
    const int m0 = blockIdx.y << 7;
    const int n0 = blockIdx.x << 7;
    const int z  = blockIdx.z;

    const bf16* Bh = BhB + (size_t)z * D_MODEL * D_MODEL;
    const bf16* Bl = BlB + (size_t)z * D_MODEL * D_MODEL;

    float acc[16][4];
    #pragma unroll
    for (int i = 0; i < 16; i++)
        #pragma unroll
        for (int j = 0; j < 4; j++) acc[i][j] = 0.f;

    // prologue: 2 stages in flight
    gload9(sb,        Ah, Al, Bh, Bl, m0, n0, 0,  tid);
    CP_COMMIT();
    gload9(sb + STG9, Ah, Al, Bh, Bl, m0, n0, 32, tid);
    CP_COMMIT();

    #pragma unroll 1
    for (int s = 0; s < NST9; s++) {
        if (s < NST9 - 2) CP_WAIT1();
        else              CP_WAIT0();
        __syncthreads();
        if (s + 2 < NST9) {
            int slot = (s + 2) % 3;
            gload9(sb + slot * STG9, Ah, Al, Bh, Bl,
                   m0, n0, (s + 2) << 5, tid);
            CP_COMMIT();
        }
        const uint32_t base = sb + (s % 3) * STG9;
        gpass9(acc, base, base + ABYT9,
               base + 2 * ABYT9, base + 2 * ABYT9 + BBYT9,
               wm, wn, lr, lc);
    }

    const int g = lane >> 2, tg = lane & 3;
    const float scale = (MODE == 1 && z == 0) ? QSC : 1.0f;
    bf16* Ch = (z == 0) ? Ch0 : (z == 1) ? Ch1 : Ch2;
    bf16* Cl = (z == 0) ? Cl0 : (z == 1) ? Cl1 : Cl2;

    #pragma unroll
    for (int mt = 0; mt < 2; mt++) {
        int row = m0 + wm * 32 + mt * 16 + g;
        #pragma unroll
        for (int nt = 0; nt < 8; nt++) {
            int col = n0 + wn * 64 + nt * 8 + tg * 2;
            float* ac = acc[mt * 8 + nt];
            if (MODE == 0) {
                float* cp = &C[(size_t)row * D_MODEL + col];
                *(float2*)cp = make_float2(ac[0], ac[1]);
                *(float2*)(cp + 8 * D_MODEL) = make_float2(ac[2], ac[3]);
            } else {
                float v0 = ac[0] * scale, v1 = ac[1] * scale;
                float v2 = ac[2] * scale, v3 = ac[3] * scale;
                uint32_t h01 = pk2(v0, v1), h23 = pk2(v2, v3);
                float2 f01 = upk2(h01), f23 = upk2(h23);
                size_t o0 = (size_t)row * D_MODEL + col;
                size_t o1 = o0 + 8 * D_MODEL;
                *(uint32_t*)&Ch[o0] = h01;
                *(uint32_t*)&Ch[o1] = h23;
                *(uint32_t*)&Cl[o0] = pk2(v0 - f01.x, v1 - f01.y);
                *(uint32_t*)&Cl[o1] = pk2(v2 - f23.x, v3 - f23.y);
            }
        }
    }
}

// ============================================================
// attn_mma4: flash attention, 128 queries/CTA, 4 warps x 32 q-rows
// (same per-warp amortization as attn_mma2), smem 110.5KB ->
// TWO CTAs PER SM: one CTA's softmax overlaps the other's mma.
// ============================================================
#define AST 144
#define QTB4  (128 * AST)                // one 128x64 bf16 Q tile = 18432
#define KVB   (64 * AST)                 // one 64x64 bf16 tile = 9216
#define KVST  (4 * KVB)                  // Kh,Kl,Vh,Vl per stage = 36864
#define KVOFF4 (2 * QTB4)                // 36864
#define ATT_SMEM (KVOFF4 + 2 * KVST)     // 110592 -> 2 CTAs/SM

__device__ __forceinline__ void kvload4(uint32_t st,
    const bf16* __restrict__ Kh, const bf16* __restrict__ Kl,
    const bf16* __restrict__ Vh, const bf16* __restrict__ Vl,
    size_t gbase, int tid)
{
    #pragma unroll
    for (int t = 0; t < 4; t++) {            // 512 chunks per tensor, 128 thr
        int idx = tid + (t << 7);
        int r = idx >> 3, c = idx & 7;
        size_t go = gbase + (size_t)r * D_MODEL + c * 8;
        uint32_t so = st + r * AST + c * 16;
        cpa16(so,           Kh + go);
        cpa16(so + KVB,     Kl + go);
        cpa16(so + 2 * KVB, Vh + go);
        cpa16(so + 3 * KVB, Vl + go);
    }
}

__global__ __launch_bounds__(128, 2) void attn_mma4(
    const bf16* __restrict__ Qh, const bf16* __restrict__ Ql,
    const bf16* __restrict__ Kh, const bf16* __restrict__ Kl,
    const bf16* __restrict__ Vh, const bf16* __restrict__ Vl,
    bf16* __restrict__ Oh, bf16* __restrict__ Ol)
{
    extern __shared__ char dsm[];
    const uint32_t sb = smem_u32(dsm);

    const int tid = threadIdx.x;
    const int wid = tid >> 5;                // 0..3, 32 q-rows each
    const int lane = tid & 31;
    const int lr = lane & 15, lc = lane >> 4;
    const int g = lane >> 2, tg = lane & 3;
    const int qb = blockIdx.x, h = blockIdx.y, b = blockIdx.z;
    const size_t qrow0 = (size_t)(b * SEQ + qb * 128);
    const size_t hcol = h * DH;

    // ---- load Q tiles (128x64 hi + lo), 128 threads ----
    #pragma unroll
    for (int t = 0; t < 8; t++) {
        int idx = tid + (t << 7);
        int r = idx >> 3, c = idx & 7;
        size_t go = (qrow0 + r) * D_MODEL + hcol + c * 8;
        uint32_t so = sb + r * AST + c * 16;
        cpa16(so, Qh + go);
        cpa16(so + QTB4, Ql + go);
    }
    CP_COMMIT();

    kvload4(sb + KVOFF4, Kh, Kl, Vh, Vl, (size_t)(b * SEQ) * D_MODEL + hcol, tid);
    CP_COMMIT();

    float acco[16][4];
    #pragma unroll
    for (int i = 0; i < 16; i++)
        #pragma unroll
        for (int j = 0; j < 4; j++) acco[i][j] = 0.f;
    float mrow[4] = {-1e30f, -1e30f, -1e30f, -1e30f};
    float lrow[4] = {0.f, 0.f, 0.f, 0.f};

    #pragma unroll 1
    for (int kb = 0; kb < 16; kb++) {
        if (kb < 15)
            kvload4(sb + KVOFF4 + ((kb + 1) & 1) * KVST, Kh, Kl, Vh, Vl,
                    (size_t)(b * SEQ + (kb + 1) * 64) * D_MODEL + hcol, tid);
        CP_COMMIT();
        CP_WAIT1();
        __syncthreads();

        const uint32_t kst = sb + KVOFF4 + (kb & 1) * KVST;
        const uint32_t khT = kst, klT = kst + KVB;
        const uint32_t vhT = kst + 2 * KVB, vlT = kst + 3 * KVB;

        float accs[16][4];
        #pragma unroll
        for (int i = 0; i < 16; i++)
            #pragma unroll
            for (int j = 0; j < 4; j++) accs[i][j] = 0.f;

        #pragma unroll
        for (int kt = 0; kt < 4; kt++) {
            uint32_t ah[2][4], al[2][4], kfh[4][4], kfl[4][4];
            #pragma unroll
            for (int mt = 0; mt < 2; mt++) {
                uint32_t qoff = (wid * 32 + mt * 16 + lr) * AST + kt * 32 + lc * 16;
                ldsm_x4(ah[mt], sb + qoff);
                ldsm_x4(al[mt], sb + QTB4 + qoff);
            }
            #pragma unroll
            for (int j = 0; j < 4; j++) {
                uint32_t koff = (j * 16 + lr) * AST + kt * 32 + lc * 16;
                ldsm_x4(kfh[j], khT + koff);
                ldsm_x4(kfl[j], klT + koff);
            }
            // term-outer
            #pragma unroll
            for (int mt = 0; mt < 2; mt++)
                #pragma unroll
                for (int j = 0; j < 4; j++) {
                    mma16816(accs[mt * 8 + 2 * j],     ah[mt], kfh[j][0], kfh[j][2]);
                    mma16816(accs[mt * 8 + 2 * j + 1], ah[mt], kfh[j][1], kfh[j][3]);
                }
            #pragma unroll
            for (int mt = 0; mt < 2; mt++)
                #pragma unroll
                for (int j = 0; j < 4; j++) {
                    mma16816(accs[mt * 8 + 2 * j],     ah[mt], kfl[j][0], kfl[j][2]);
                    mma16816(accs[mt * 8 + 2 * j + 1], ah[mt], kfl[j][1], kfl[j][3]);
                }
            #pragma unroll
            for (int mt = 0; mt < 2; mt++)
                #pragma unroll
                for (int j = 0; j < 4; j++) {
                    mma16816(accs[mt * 8 + 2 * j],     al[mt], kfh[j][0], kfh[j][2]);
                    mma16816(accs[mt * 8 + 2 * j + 1], al[mt], kfh[j][1], kfh[j][3]);
                }
        }

        #pragma unroll
        for (int mt = 0; mt < 2; mt++) {
            float mx0 = -1e30f, mx1 = -1e30f;
            #pragma unroll
            for (int nt = 0; nt < 8; nt++) {
                mx0 = fmaxf(mx0, fmaxf(accs[mt * 8 + nt][0], accs[mt * 8 + nt][1]));
                mx1 = fmaxf(mx1, fmaxf(accs[mt * 8 + nt][2], accs[mt * 8 + nt][3]));
            }
            mx0 = fmaxf(mx0, __shfl_xor_sync(0xffffffffu, mx0, 1));
            mx0 = fmaxf(mx0, __shfl_xor_sync(0xffffffffu, mx0, 2));
            mx1 = fmaxf(mx1, __shfl_xor_sync(0xffffffffu, mx1, 1));
            mx1 = fmaxf(mx1, __shfl_xor_sync(0xffffffffu, mx1, 2));
            float mn0 = fmaxf(mrow[mt * 2],     mx0);
            float mn1 = fmaxf(mrow[mt * 2 + 1], mx1);
            float al0 = ex2f(mrow[mt * 2]     - mn0);
            float al1 = ex2f(mrow[mt * 2 + 1] - mn1);
            mrow[mt * 2] = mn0; mrow[mt * 2 + 1] = mn1;
            float s0 = 0.f, s1 = 0.f;
            #pragma unroll
            for (int nt = 0; nt < 8; nt++) {
                float* a = accs[mt * 8 + nt];
                a[0] = ex2f(a[0] - mn0);
                a[1] = ex2f(a[1] - mn0);
                a[2] = ex2f(a[2] - mn1);
                a[3] = ex2f(a[3] - mn1);
                s0 += a[0] + a[1];
                s1 += a[2] + a[3];
            }
            s0 += __shfl_xor_sync(0xffffffffu, s0, 1);
            s0 += __shfl_xor_sync(0xffffffffu, s0, 2);
            s1 += __shfl_xor_sync(0xffffffffu, s1, 1);
            s1 += __shfl_xor_sync(0xffffffffu, s1, 2);
            lrow[mt * 2]     = lrow[mt * 2]     * al0 + s0;
            lrow[mt * 2 + 1] = lrow[mt * 2 + 1] * al1 + s1;
            #pragma unroll
            for (int nt = 0; nt < 8; nt++) {
                acco[mt * 8 + nt][0] *= al0; acco[mt * 8 + nt][1] *= al0;
                acco[mt * 8 + nt][2] *= al1; acco[mt * 8 + nt][3] *= al1;
            }
        }

        // ---- O += P V, 3-split, term-outer ----
        #pragma unroll
        for (int kt = 0; kt < 4; kt++) {
            uint32_t vbh[4][4], vbl[4][4];
            #pragma unroll
            for (int cg = 0; cg < 4; cg++) {
                uint32_t voff = (kt * 16 + lr) * AST + cg * 32 + lc * 16;
                ldsm_x4t(vbh[cg], vhT + voff);
                ldsm_x4t(vbl[cg], vlT + voff);
            }
            uint32_t ph[2][4], pl[2][4];
            #pragma unroll
            for (int mt = 0; mt < 2; mt++) {
                float* s0 = accs[mt * 8 + 2 * kt];
                float* s1 = accs[mt * 8 + 2 * kt + 1];
                ph[mt][0] = pk2(s0[0], s0[1]);
                ph[mt][1] = pk2(s0[2], s0[3]);
                ph[mt][2] = pk2(s1[0], s1[1]);
                ph[mt][3] = pk2(s1[2], s1[3]);
                float2 f0 = upk2(ph[mt][0]), f1 = upk2(ph[mt][1]);
                float2 f2 = upk2(ph[mt][2]), f3 = upk2(ph[mt][3]);
                pl[mt][0] = pk2(s0[0] - f0.x, s0[1] - f0.y);
                pl[mt][1] = pk2(s0[2] - f1.x, s0[3] - f1.y);
                pl[mt][2] = pk2(s1[0] - f2.x, s1[1] - f2.y);
                pl[mt][3] = pk2(s1[2] - f3.x, s1[3] - f3.y);
            }
            #pragma unroll
            for (int mt = 0; mt < 2; mt++)
                #pragma unroll
                for (int nt = 0; nt < 8; nt++)
                    mma16816(acco[mt * 8 + nt], ph[mt],
                             vbh[nt >> 1][(nt & 1) * 2],
                             vbh[nt >> 1][(nt & 1) * 2 + 1]);
            #pragma unroll
            for (int mt = 0; mt < 2; mt++)
                #pragma unroll
                for (int nt = 0; nt < 8; nt++)
                    mma16816(acco[mt * 8 + nt], pl[mt],
                             vbh[nt >> 1][(nt & 1) * 2],
                             vbh[nt >> 1][(nt & 1) * 2 + 1]);
            #pragma unroll
            for (int mt = 0; mt < 2; mt++)
                #pragma unroll
                for (int nt = 0; nt < 8; nt++)
                    mma16816(acco[mt * 8 + nt], ph[mt],
                             vbl[nt >> 1][(nt & 1) * 2],
                             vbl[nt >> 1][(nt & 1) * 2 + 1]);
        }
        __syncthreads();
    }

    #pragma unroll
    for (int mt = 0; mt < 2; mt++) {
        float inv0 = 1.f / lrow[mt * 2];
        float inv1 = 1.f / lrow[mt * 2 + 1];
        size_t r0 = (qrow0 + wid * 32 + mt * 16 + g) * D_MODEL + hcol;
        size_t r1 = r0 + 8 * D_MODEL;
        #pragma unroll
        for (int nt = 0; nt < 8; nt++) {
            int col = nt * 8 + tg * 2;
            float v0 = acco[mt * 8 + nt][0] * inv0;
            float v1 = acco[mt * 8 + nt][1] * inv0;
            float v2 = acco[mt * 8 + nt][2] * inv1;
            float v3 = acco[mt * 8 + nt][3] * inv1;
            uint32_t h01 = pk2(v0, v1), h23 = pk2(v2, v3);
            float2 f01 = upk2(h01), f23 = upk2(h23);
            *(uint32_t*)&Oh[r0 + col] = h01;
            *(uint32_t*)&Oh[r1 + col] = h23;
            *(uint32_t*)&Ol[r0 + col] = pk2(v0 - f01.x, v1 - f01.y);
            *(uint32_t*)&Ol[r1 + col] = pk2(v2 - f23.x, v3 - f23.y);
        }
    }
}

// ============================================================
extern "C" void kernel_launch(void* const* d_in, const int* in_sizes, int n_in,
                              void* d_out, int out_size)
{
    const float* x = (const float*)d_in[0];
    float* out = (float*)d_out;

    bf16 *xh, *xl, *qh, *ql, *kh, *kl, *vh, *vl, *oh, *ol, *bh, *bl;
    cudaGetSymbolAddress((void**)&xh, g_xh);
    cudaGetSymbolAddress((void**)&xl, g_xl);
    cudaGetSymbolAddress((void**)&qh, g_Qh);
    cudaGetSymbolAddress((void**)&ql, g_Ql);
    cudaGetSymbolAddress((void**)&kh, g_Kh);
    cudaGetSymbolAddress((void**)&kl, g_Kl);
    cudaGetSymbolAddress((void**)&vh, g_Vh);
    cudaGetSymbolAddress((void**)&vl, g_Vl);
    cudaGetSymbolAddress((void**)&oh, g_Oh);
    cudaGetSymbolAddress((void**)&ol, g_Ol);
    cudaGetSymbolAddress((void**)&bh, g_Wh);
    cudaGetSymbolAddress((void**)&bl, g_Wl);
    const size_t WSTR = (size_t)D_MODEL * D_MODEL;

    static int cfg_done = 0;
    if (!cfg_done) {
        cudaFuncSetAttribute(hgemm9<0>,
            cudaFuncAttributeMaxDynamicSharedMemorySize, GEM_SMEM);
        cudaFuncSetAttribute(hgemm9<1>,
            cudaFuncAttributeMaxDynamicSharedMemorySize, GEM_SMEM);
        cudaFuncSetAttribute(attn_mma4,
            cudaFuncAttributeMaxDynamicSharedMemorySize, ATT_SMEM);
        cfg_done = 1;
    }

    // splits: x, then all 4 weights in one launch
    fsplit<<<MROWS * D_MODEL / 1024, 256>>>(x, xh, xl);
    wsplit4<<<dim3(D_MODEL * D_MODEL / 1024, 1, 4), 256>>>(
        (const float*)d_in[1], (const float*)d_in[2],
        (const float*)d_in[3], (const float*)d_in[4], bh, bl);

    // QKV projections fused into one launch (grid.z selects W / output)
    hgemm9<1><<<dim3(D_MODEL / 128, MROWS / 128, 3), 256, GEM_SMEM>>>(
        xh, xl, bh, bl, nullptr, qh, ql, kh, kl, vh, vl);

    attn_mma4<<<dim3(SEQ / 128, HEADS, BATCH), 128, ATT_SMEM>>>(
        qh, ql, kh, kl, vh, vl, oh, ol);

    // final projection (W index 3)
    hgemm9<0><<<dim3(D_MODEL / 128, MROWS / 128, 1), 256, GEM_SMEM>>>(
        oh, ol, bh + 3 * WSTR, bl + 3 * WSTR, out,
        nullptr, nullptr, nullptr, nullptr, nullptr, nullptr);
}